// round 12
// baseline (speedup 1.0000x reference)
#include <cuda_runtime.h>
#include <cuda_fp16.h>
#include <cstdint>

#define Bv   4
#define Tv   2048
#define Dv   1024
#define Hv   8
#define DHv  128
#define Kv   4
#define DFFv 1365
#define DFFP 1408
#define BT   (Bv*Tv)
#define BTD  ((size_t)BT*Dv)
#define BTF  ((size_t)BT*DFFP)

// ---------------- fp32 scratch ----------------
#define F_WZ    ((size_t)0)
#define F_WI    (BTD)
#define F_WF    ((size_t)2*BTD)
#define F_WO    ((size_t)3*BTD)
#define F_HSEQ  ((size_t)4*BTD)
#define F_HSKIP ((size_t)5*BTD)
#define F_ZL    ((size_t)6*BTD)
#define F_ZR    ((size_t)6*BTD + BTF)
#define F_TOTAL ((size_t)6*BTD + 2*BTF)
__device__ __align__(256) float g_f32[F_TOTAL];

// ---------------- fp16 scratch (lo planes pre-scaled by 2048) ----------------
#define G_XNH   ((size_t)0)
#define G_XNL   (BTD)
#define G_XIFH  ((size_t)2*BTD)
#define G_XIFL  ((size_t)3*BTD)
#define G_HNH   ((size_t)4*BTD)
#define G_HNL   ((size_t)5*BTD)
#define G_ZLH   ((size_t)6*BTD)
#define G_ZLL   ((size_t)6*BTD + BTF)
#define G_WPH   ((size_t)6*BTD + 2*BTF)
#define G_WPL   (G_WPH + (size_t)4*Dv*Dv)
#define G_WTH   (G_WPL + (size_t)4*Dv*Dv)
#define G_WTL   (G_WTH + (size_t)4*Hv*DHv*DHv)
#define G_L     (G_WTL + (size_t)4*Hv*DHv*DHv)
#define G_R     (G_L + (size_t)DFFv*Dv)
#define G_WL    (G_R + (size_t)DFFv*Dv)
#define G_TOTAL (G_WL + (size_t)Dv*DFFP)
__device__ __align__(256) __half g_f16[G_TOTAL];

#define LO_SCALE 2048.0f
#define LO_INV   4.8828125e-4f

__device__ __forceinline__ float gelu_exact(float x) {
    return 0.5f * x * (1.0f + erff(x * 0.70710678118654752f));
}
// lo plane scaled by 2048 so fp16-accumulated corrections stay in normal range
__device__ __forceinline__ void split2h(float v, __half& h, __half& l) {
    h = __float2half_rn(v);
    l = __float2half_rn((v - __half2float(h)) * LO_SCALE);
}

// ---------------- LayerNorm (+res), outputs fp32 and/or fp16 hi/lo ----------------
__global__ void ln_kernel(const float* __restrict__ in, const float* __restrict__ g,
                          const float* __restrict__ bb, const float* __restrict__ res,
                          float* __restrict__ out,
                          __half* __restrict__ oh, __half* __restrict__ ol)
{
    int row = blockIdx.x;
    int t = threadIdx.x;
    const float4 v = ((const float4*)(in + (size_t)row * Dv))[t];
    float s = v.x + v.y + v.z + v.w;
#pragma unroll
    for (int o = 16; o > 0; o >>= 1) s += __shfl_down_sync(0xffffffffu, s, o);
    __shared__ float red[8];
    __shared__ float bc[2];
    int wid = t >> 5;
    if ((t & 31) == 0) red[wid] = s;
    __syncthreads();
    if (t == 0) {
        float S = 0.f;
#pragma unroll
        for (int i = 0; i < 8; i++) S += red[i];
        bc[0] = S * (1.f / 1024.f);
    }
    __syncthreads();
    float mu = bc[0];
    float dx = v.x - mu, dy = v.y - mu, dz = v.z - mu, dw = v.w - mu;
    float q = dx*dx + dy*dy + dz*dz + dw*dw;
#pragma unroll
    for (int o = 16; o > 0; o >>= 1) q += __shfl_down_sync(0xffffffffu, q, o);
    if ((t & 31) == 0) red[wid] = q;
    __syncthreads();
    if (t == 0) {
        float Q = 0.f;
#pragma unroll
        for (int i = 0; i < 8; i++) Q += red[i];
        bc[1] = rsqrtf(Q * (1.f / 1024.f) + 1e-5f);
    }
    __syncthreads();
    float rs = bc[1];
    float4 gv = ((const float4*)g)[t];
    float4 bv = ((const float4*)bb)[t];
    float o4[4];
    o4[0] = dx * rs * gv.x + bv.x;
    o4[1] = dy * rs * gv.y + bv.y;
    o4[2] = dz * rs * gv.z + bv.z;
    o4[3] = dw * rs * gv.w + bv.w;
    if (res) {
        float4 rv = ((const float4*)(res + (size_t)row * Dv))[t];
        o4[0] += rv.x; o4[1] += rv.y; o4[2] += rv.z; o4[3] += rv.w;
    }
    if (out) {
        float4 w = make_float4(o4[0], o4[1], o4[2], o4[3]);
        ((float4*)(out + (size_t)row * Dv))[t] = w;
    }
    if (oh) {
        __half hh[4], ll[4];
#pragma unroll
        for (int i = 0; i < 4; i++) split2h(o4[i], hh[i], ll[i]);
        size_t o = (size_t)row * Dv + t * 4;
        *(uint64_t*)(oh + o) = *(uint64_t*)hh;
        *(uint64_t*)(ol + o) = *(uint64_t*)ll;
    }
}

// ---------------- weight prep ----------------
__global__ void repack_conv_split(const float* __restrict__ w,
                                  __half* __restrict__ oh, __half* __restrict__ ol)
{
    int idx = blockIdx.x * 256 + threadIdx.x;
    if (idx < 4 * Dv * Dv) {
        int k = idx >> 20;
        int rem = idx & ((1 << 20) - 1);
        int o = rem >> 10, i = rem & 1023;
        split2h(w[((size_t)(o * Dv + i)) * Kv + k], oh[idx], ol[idx]);
    }
}

__global__ void repack_bd_split(const float* __restrict__ Wz, const float* __restrict__ Wi,
                                const float* __restrict__ Wf, const float* __restrict__ Wo,
                                __half* __restrict__ oh, __half* __restrict__ ol)
{
    int idx = blockIdx.x * 256 + threadIdx.x;
    if (idx < 4 * Hv * DHv * DHv) {
        int gate = idx >> 17;
        int rem = idx & ((1 << 17) - 1);
        int head = rem >> 14;
        int rem2 = rem & ((1 << 14) - 1);
        int e = rem2 >> 7, d = rem2 & 127;
        const float* W = (gate == 0) ? Wz : (gate == 1) ? Wi : (gate == 2) ? Wf : Wo;
        split2h(W[(head * 128 + d) * 128 + e], oh[idx], ol[idx]);
    }
}

__global__ void lr_half_kernel(const float* __restrict__ lw, const float* __restrict__ rw,
                               __half* __restrict__ lo, __half* __restrict__ ro)
{
    int idx = blockIdx.x * 256 + threadIdx.x;
    if (idx < DFFv * Dv) {
        lo[idx] = __float2half_rn(lw[idx]);
        ro[idx] = __float2half_rn(rw[idx]);
    }
}

__global__ void repack_last_h(const float* __restrict__ w, __half* __restrict__ o16)
{
    int idx = blockIdx.x * 256 + threadIdx.x;
    if (idx < Dv * DFFv) {
        int o = idx / DFFv, i = idx - o * DFFv;
        o16[(size_t)o * DFFP + i] = __float2half_rn(w[idx]);
    }
}

__global__ void mul_split(const float* __restrict__ zl, const float* __restrict__ zr,
                          __half* __restrict__ oh, __half* __restrict__ ol)
{
    int c = blockIdx.x * 256 + threadIdx.x;
    if (c < DFFv) {
        size_t i = (size_t)blockIdx.y * DFFP + c;
        split2h(zl[i] * zr[i], oh[i], ol[i]);
    }
}

// ====== fp16 mma.sync GEMM, fp32-acc main pass + fp16-acc correction passes ======
#define PITCH 72
#define PLANE (128 * PITCH * 2)          // 18432 B
#define GSMEM3 (2 * 4 * PLANE)           // 147456
#define GSMEM2 (2 * 3 * PLANE)           // 110592

__device__ __forceinline__ void ldsm_x4(uint32_t* r, uint32_t addr) {
    asm volatile("ldmatrix.sync.aligned.m8n8.x4.shared.b16 {%0,%1,%2,%3},[%4];"
                 : "=r"(r[0]), "=r"(r[1]), "=r"(r[2]), "=r"(r[3]) : "r"(addr));
}
__device__ __forceinline__ void mma_f32acc(float* d, const uint32_t* a, const uint32_t* b) {
    asm volatile("mma.sync.aligned.m16n8k16.row.col.f32.f16.f16.f32 "
                 "{%0,%1,%2,%3},{%4,%5,%6,%7},{%8,%9},{%0,%1,%2,%3};"
                 : "+f"(d[0]), "+f"(d[1]), "+f"(d[2]), "+f"(d[3])
                 : "r"(a[0]), "r"(a[1]), "r"(a[2]), "r"(a[3]), "r"(b[0]), "r"(b[1]));
}
__device__ __forceinline__ void mma_f16acc(uint32_t* d, const uint32_t* a, const uint32_t* b) {
    asm volatile("mma.sync.aligned.m16n8k16.row.col.f16.f16.f16.f16 "
                 "{%0,%1},{%2,%3,%4,%5},{%6,%7},{%0,%1};"
                 : "+r"(d[0]), "+r"(d[1])
                 : "r"(a[0]), "r"(a[1]), "r"(a[2]), "r"(a[3]), "r"(b[0]), "r"(b[1]));
}
__device__ __forceinline__ void cpa16(uint32_t dst, const void* src, bool pred) {
    int sz = pred ? 16 : 0;
    asm volatile("cp.async.cg.shared.global [%0], [%1], 16, %2;"
                 :: "r"(dst), "l"(src), "r"(sz) : "memory");
}

struct GArgs {
    const __half *Ah[4], *Al[4], *Bw[4], *Bl[4];
    int shift[4];
    int npass, lda, ldb, K;
    float* C; int ldc;
    const float* bias;
    const float* res; int ldres;
    int N; int act;                  // 0 none, 1 gelu, 2 swish
    __half *Oh, *Ol; int ldo;        // split fp16 output instead of C
};

template<bool SPLITB>
__device__ __forceinline__ void stage_chunk(uint32_t buf, const GArgs& a,
                                            int pass, int k0, int row0, int col0)
{
    const int tid = threadIdx.x;
    const int r = tid >> 1;
    const int half = tid & 1;
    const uint32_t dst0 = buf + r * (PITCH * 2) + half * 64;

    int shift = a.shift[pass];
    int grow = row0 + r;
    bool pA = (shift == 0) || ((grow & (Tv - 1)) >= shift);
    int arow = pA ? (grow - shift) : 0;
    const __half* sAh = a.Ah[pass] + (size_t)arow * a.lda + k0 + half * 32;
    const __half* sAl = a.Al[pass] + (size_t)arow * a.lda + k0 + half * 32;
#pragma unroll
    for (int v = 0; v < 4; v++) cpa16(dst0 + v * 16, sAh + v * 8, pA);
#pragma unroll
    for (int v = 0; v < 4; v++) cpa16(dst0 + PLANE + v * 16, sAl + v * 8, pA);

    int gn = col0 + r;
    bool pB = (gn < a.N);
    int brow = pB ? gn : 0;
    const __half* sB = a.Bw[pass] + (size_t)brow * a.ldb + k0 + half * 32;
#pragma unroll
    for (int v = 0; v < 4; v++) cpa16(dst0 + 2 * PLANE + v * 16, sB + v * 8, pB);
    if (SPLITB) {
        const __half* sBl = a.Bl[pass] + (size_t)brow * a.ldb + k0 + half * 32;
#pragma unroll
        for (int v = 0; v < 4; v++) cpa16(dst0 + 3 * PLANE + v * 16, sBl + v * 8, pB);
    }
}

template<bool SPLITB>
__device__ void mma_gemm_body(const GArgs& a, int bm, int bn)
{
    constexpr int BSZ = (SPLITB ? 4 : 3) * PLANE;
    extern __shared__ char dsm[];
    const uint32_t sb = (uint32_t)__cvta_generic_to_shared(dsm);
    const int tid = threadIdx.x;
    const int lane = tid & 31;
    const int warp = tid >> 5;
    const int wm = warp & 3;
    const int wn = warp >> 2;
    const int row0 = bm * 128, col0 = bn * 128;

    const int lr = lane & 7, lg = lane >> 3;
    const int a_base = (wm * 32 + lr + (lg & 1) * 8) * PITCH + (lg >> 1) * 8;
    const int b_base = (wn * 64 + lr + (lg & 1) * 8) * PITCH + (lg >> 1) * 8;

    float acc[2][8][4];
    uint32_t c16[2][8][2];
#pragma unroll
    for (int i = 0; i < 2; i++)
#pragma unroll
        for (int j = 0; j < 8; j++) {
#pragma unroll
            for (int q = 0; q < 4; q++) acc[i][j][q] = 0.f;
            c16[i][j][0] = 0u; c16[i][j][1] = 0u;
        }

    const int nchunk = a.K >> 6;
    const int NIT = a.npass * nchunk;

    stage_chunk<SPLITB>(sb, a, 0, 0, row0, col0);
    asm volatile("cp.async.commit_group;" ::: "memory");

    for (int it = 0; it < NIT; it++) {
        if (it + 1 < NIT) {
            int nx = it + 1;
            int pass = nx / nchunk;
            int k0 = (nx - pass * nchunk) << 6;
            stage_chunk<SPLITB>(sb + ((nx & 1) ? BSZ : 0), a, pass, k0, row0, col0);
            asm volatile("cp.async.commit_group;" ::: "memory");
            asm volatile("cp.async.wait_group 1;" ::: "memory");
        } else {
            asm volatile("cp.async.wait_group 0;" ::: "memory");
        }
        __syncthreads();

        const uint32_t buf = sb + ((it & 1) ? BSZ : 0);
#pragma unroll
        for (int ks = 0; ks < 64; ks += 16) {
            uint32_t ah[2][4], al[2][4];
#pragma unroll
            for (int am = 0; am < 2; am++) {
                int ei = a_base + am * 16 * PITCH + ks;
                ldsm_x4(ah[am], buf + ei * 2);
                ldsm_x4(al[am], buf + PLANE + ei * 2);
            }
#pragma unroll
            for (int p = 0; p < 4; p++) {
                int ei = b_base + p * 16 * PITCH + ks;
                uint32_t b4[4];
                ldsm_x4(b4, buf + 2 * PLANE + ei * 2);
                uint32_t bl4[4];
                if (SPLITB) ldsm_x4(bl4, buf + 3 * PLANE + ei * 2);
#pragma unroll
                for (int sub = 0; sub < 2; sub++) {
                    uint32_t bh[2] = { b4[sub], b4[2 + sub] };
#pragma unroll
                    for (int am = 0; am < 2; am++) {
                        mma_f32acc(acc[am][p * 2 + sub], ah[am], bh);
                        mma_f16acc(c16[am][p * 2 + sub], al[am], bh);
                    }
                    if (SPLITB) {
                        uint32_t bl[2] = { bl4[sub], bl4[2 + sub] };
#pragma unroll
                        for (int am = 0; am < 2; am++)
                            mma_f16acc(c16[am][p * 2 + sub], ah[am], bl);
                    }
                }
            }
        }
        __syncthreads();
    }

    // ---- epilogue: merge fp16-acc corrections (scaled by 1/2048) ----
#pragma unroll
    for (int am = 0; am < 2; am++) {
#pragma unroll
        for (int bi = 0; bi < 8; bi++) {
            int gr0 = row0 + wm * 32 + am * 16 + (lane >> 2);
            int gc = col0 + wn * 64 + bi * 8 + (lane & 3) * 2;
            float* d = acc[am][bi];
#pragma unroll
            for (int h = 0; h < 2; h++) {
                int gr = gr0 + h * 8;
                __half2 ch = *reinterpret_cast<__half2*>(&c16[am][bi][h]);
                float2 cf = __half22float2(ch);
                float v0 = d[h * 2 + 0] + cf.x * LO_INV;
                float v1 = d[h * 2 + 1] + cf.y * LO_INV;
                bool ok0 = (gc < a.N), ok1 = (gc + 1 < a.N);
                if (a.bias) {
                    if (ok0) v0 += a.bias[gc];
                    if (ok1) v1 += a.bias[gc + 1];
                }
                if (a.act == 1) { v0 = gelu_exact(v0); v1 = gelu_exact(v1); }
                else if (a.act == 2) {
                    v0 = v0 / (1.f + expf(-v0));
                    v1 = v1 / (1.f + expf(-v1));
                }
                if (a.Oh) {
                    size_t o = (size_t)gr * a.ldo + gc;
                    __half hh, ll;
                    if (ok0) { split2h(v0, hh, ll); a.Oh[o] = hh; a.Ol[o] = ll; }
                    if (ok1) { split2h(v1, hh, ll); a.Oh[o + 1] = hh; a.Ol[o + 1] = ll; }
                } else {
                    size_t o = (size_t)gr * a.ldc + gc;
                    if (a.res) {
                        size_t ro = (size_t)gr * a.ldres + gc;
                        if (ok0) v0 += a.res[ro];
                        if (ok1) v1 += a.res[ro + 1];
                    }
                    if (ok0) a.C[o] = v0;
                    if (ok1) a.C[o + 1] = v1;
                }
            }
        }
    }
}

__global__ void __launch_bounds__(256, 1)
mma_gemm3_kernel(GArgs a)   // B split (conv / proj precision)
{
    mma_gemm_body<true>(a, blockIdx.x, blockIdx.y);
}

__global__ void __launch_bounds__(256, 1)
mma_gemm2_kernel(GArgs a)   // B plain (GLU / last)
{
    mma_gemm_body<false>(a, blockIdx.x, blockIdx.y);
}

__global__ void __launch_bounds__(256, 1)
mma_proj_kernel(const __half* xnh, const __half* xnl,
                const __half* xifh, const __half* xifl,
                const __half* wth, const __half* wtl,
                float* wz, float* wi, float* wf, float* wo,
                const float* bz, const float* bi, const float* bf, const float* bo)
{
    int z = blockIdx.z;
    int gate = z >> 3, head = z & 7;
    GArgs a;
    bool useif = (gate == 1 || gate == 2);
    a.Ah[0] = (useif ? xifh : xnh) + head * 128;
    a.Al[0] = (useif ? xifl : xnl) + head * 128;
    a.Bw[0] = wth + (size_t)z * 16384;
    a.Bl[0] = wtl + (size_t)z * 16384;
    a.shift[0] = 0; a.npass = 1;
    a.lda = Dv; a.ldb = 128; a.K = 128;
    float* Cs = (gate == 0) ? wz : (gate == 1) ? wi : (gate == 2) ? wf : wo;
    const float* bs = (gate == 0) ? bz : (gate == 1) ? bi : (gate == 2) ? bf : bo;
    a.C = Cs + head * 128; a.ldc = Dv;
    a.bias = bs + head * 128;
    a.res = nullptr; a.ldres = 0;
    a.N = 128; a.act = 0;
    a.Oh = nullptr; a.Ol = nullptr; a.ldo = 0;
    mma_gemm_body<true>(a, blockIdx.x, 0);
}

// ---------------- sLSTM scan: tagged DSMEM exchange, no cluster barrier ----------
__device__ __forceinline__ uint32_t smem_u32(const void* p) {
    return (uint32_t)__cvta_generic_to_shared(p);
}
__device__ __forceinline__ uint32_t mapa_u32(uint32_t addr, uint32_t rank) {
    uint32_t r;
    asm("mapa.shared::cluster.u32 %0, %1, %2;" : "=r"(r) : "r"(addr), "r"(rank));
    return r;
}
__device__ __forceinline__ uint32_t ctarank() {
    uint32_t r; asm("mov.u32 %0, %%cluster_ctarank;" : "=r"(r)); return r;
}
__device__ __forceinline__ void cluster_sync_() {
    asm volatile("barrier.cluster.arrive.aligned;" ::: "memory");
    asm volatile("barrier.cluster.wait.aligned;" ::: "memory");
}
__device__ __forceinline__ void st_cluster_b64(uint32_t addr, unsigned long long v) {
    asm volatile("st.shared::cluster.b64 [%0], %1;" :: "r"(addr), "l"(v) : "memory");
}
__device__ __forceinline__ float poll64(uint32_t addr, uint32_t tag) {
    uint32_t lo, hi;
    do {
        asm volatile("ld.volatile.shared.v2.u32 {%0,%1},[%2];"
                     : "=r"(lo), "=r"(hi) : "r"(addr));
    } while (hi != tag);
    return __uint_as_float(lo);
}

__global__ void __cluster_dims__(4, 1, 1) __launch_bounds__(128, 1)
scan_kernel(const float* __restrict__ Rz, const float* __restrict__ Ri,
            const float* __restrict__ Rf, const float* __restrict__ Ro,
            const float* __restrict__ wz, const float* __restrict__ wi,
            const float* __restrict__ wf, const float* __restrict__ wo,
            float* __restrict__ hseq, float* __restrict__ stout, int write_states)
{
    __shared__ float sm_h[2][128];
    __shared__ __align__(8) unsigned long long sm_slot[2][4][128];

    const int e = threadIdx.x;
    const uint32_t rank = ctarank();               // 0=z 1=i 2=f 3=o
    const int cid = blockIdx.x >> 2;
    const int b = cid >> 3, head = cid & 7;

    const float* Rsel = (rank == 0) ? Rz : (rank == 1) ? Ri : (rank == 2) ? Rf : Ro;
    const float* wsel = (rank == 0) ? wz : (rank == 1) ? wi : (rank == 2) ? wf : wo;

    float Rcol[128];
#pragma unroll
    for (int d = 0; d < 128; d++) Rcol[d] = Rsel[(head * 128 + d) * 128 + e];

    sm_h[0][e] = 0.f;
    sm_h[1][e] = 0.f;
#pragma unroll
    for (int p = 0; p < 2; p++)
#pragma unroll
        for (int g = 0; g < 4; g++) sm_slot[p][g][e] = 0xFFFFFFFFFFFFFFFFULL;

    float c = 0.f, n = 0.f, m = 0.f;

    uint32_t myaddr = smem_u32(&sm_slot[0][rank][e]);
    uint32_t dst[4];
#pragma unroll
    for (int r = 0; r < 4; r++) dst[r] = mapa_u32(myaddr, (uint32_t)r);

    uint32_t pbase[4];
#pragma unroll
    for (int g = 0; g < 4; g++) pbase[g] = smem_u32(&sm_slot[0][g][e]);

    const float* wptr = wsel + ((size_t)b * Tv) * Dv + head * 128 + e;
    float* hout = hseq + ((size_t)b * Tv) * Dv + head * 128 + e;

    __syncthreads();
    cluster_sync_();        // slots initialized cluster-wide before any store

    float wv = wptr[0];
    for (int t = 0; t < Tv; t++) {
        const int rp = t & 1;
        const float4* h4 = (const float4*)sm_h[rp];
        float a0 = 0.f, a1 = 0.f, a2 = 0.f, a3 = 0.f;
#pragma unroll
        for (int d = 0; d < 32; d++) {
            float4 hv = h4[d];
            a0 = fmaf(hv.x, Rcol[4 * d + 0], a0);
            a1 = fmaf(hv.y, Rcol[4 * d + 1], a1);
            a2 = fmaf(hv.z, Rcol[4 * d + 2], a2);
            a3 = fmaf(hv.w, Rcol[4 * d + 3], a3);
        }
        float bar = wv + ((a0 + a1) + (a2 + a3));

        const uint32_t tag = (uint32_t)(t + 1);
        unsigned long long pkt = ((unsigned long long)tag << 32) | __float_as_uint(bar);
        const uint32_t poff = (uint32_t)rp * (4 * 128 * 8);
#pragma unroll
        for (int r = 0; r < 4; r++) st_cluster_b64(dst[r] + poff, pkt);

        if (t + 1 < Tv) wv = wptr[(size_t)(t + 1) * Dv];   // prefetch next w

        float zb = poll64(pbase[0] + poff, tag);
        float ib = poll64(pbase[1] + poff, tag);
        float fb = poll64(pbase[2] + poff, tag);
        float ob = poll64(pbase[3] + poff, tag);

        float z  = tanhf(zb);
        float o  = 1.f / (1.f + expf(-ob));
        float mn = fmaxf(fb + m, ib);
        float iv = expf(ib - mn);
        float fv = expf(fb + m - mn);
        c = fv * c + iv * z;
        n = fv * n + iv;
        m = mn;
        float h = o * (c / fmaxf(fabsf(n), 1e-8f));

        if (rank == 0) hout[(size_t)t * Dv] = h;
        sm_h[rp ^ 1][e] = h;
        __syncthreads();
    }

    if (rank == 0 && write_states) {
        int off = b * Dv + head * 128 + e;
        stout[off]          = sm_h[Tv & 1][e];
        stout[4096 + off]   = c;
        stout[8192 + off]   = n;
        stout[12288 + off]  = m;
    }
    cluster_sync_();
}

// ---------------- launch ----------------
extern "C" void kernel_launch(void* const* d_in, const int* in_sizes, int n_in,
                              void* d_out, int out_size)
{
    const float* x      = (const float*)d_in[0];
    const float* Wz     = (const float*)d_in[1];
    const float* Wi     = (const float*)d_in[2];
    const float* Wf     = (const float*)d_in[3];
    const float* Wo     = (const float*)d_in[4];
    const float* bz     = (const float*)d_in[5];
    const float* bi     = (const float*)d_in[6];
    const float* bf     = (const float*)d_in[7];
    const float* bo     = (const float*)d_in[8];
    const float* Rz     = (const float*)d_in[9];
    const float* Ri     = (const float*)d_in[10];
    const float* Rf     = (const float*)d_in[11];
    const float* Ro     = (const float*)d_in[12];
    const float* conv_w = (const float*)d_in[13];
    const float* conv_b = (const float*)d_in[14];
    const float* ln_g   = (const float*)d_in[15];
    const float* ln_b   = (const float*)d_in[16];
    const float* gn_g   = (const float*)d_in[17];
    const float* gn_b   = (const float*)d_in[18];
    const float* left_w = (const float*)d_in[19];
    const float* left_b = (const float*)d_in[20];
    const float* right_w= (const float*)d_in[21];
    const float* right_b= (const float*)d_in[22];
    const float* last_w = (const float*)d_in[23];
    const float* last_b = (const float*)d_in[24];
    float* out = (float*)d_out;

    float* F = nullptr;
    __half* G = nullptr;
    cudaGetSymbolAddress((void**)&F, g_f32);
    cudaGetSymbolAddress((void**)&G, g_f16);

    cudaFuncSetAttribute(mma_gemm3_kernel, cudaFuncAttributeMaxDynamicSharedMemorySize, GSMEM3);
    cudaFuncSetAttribute(mma_gemm2_kernel, cudaFuncAttributeMaxDynamicSharedMemorySize, GSMEM2);
    cudaFuncSetAttribute(mma_proj_kernel, cudaFuncAttributeMaxDynamicSharedMemorySize, GSMEM3);

    // my launch #4 (conv GEMM) = overall #6 under ncu -s 5 -c 1
    ln_kernel<<<BT, 256>>>(x, ln_g, ln_b, nullptr, nullptr, G + G_XNH, G + G_XNL);       // 1
    repack_conv_split<<<(4 * Dv * Dv + 255) / 256, 256>>>(conv_w, G + G_WPH, G + G_WPL); // 2
    repack_bd_split<<<(4 * Hv * DHv * DHv + 255) / 256, 256>>>(Wz, Wi, Wf, Wo,
                                                               G + G_WTH, G + G_WTL);    // 3
    // 4. causal conv: 4 shift-passes fused (split precision), + swish + split
    {
        GArgs a;
        for (int k = 0; k < 4; k++) {
            a.Ah[k] = G + G_XNH; a.Al[k] = G + G_XNL;
            a.Bw[k] = G + G_WPH + (size_t)k * Dv * Dv;
            a.Bl[k] = G + G_WPL + (size_t)k * Dv * Dv;
            a.shift[k] = 3 - k;
        }
        a.npass = 4; a.lda = Dv; a.ldb = Dv; a.K = Dv;
        a.C = nullptr; a.ldc = 0;
        a.bias = conv_b; a.res = nullptr; a.ldres = 0;
        a.N = Dv; a.act = 2;
        a.Oh = G + G_XIFH; a.Ol = G + G_XIFL; a.ldo = Dv;
        mma_gemm3_kernel<<<dim3(BT / 128, Dv / 128), 256, GSMEM3>>>(a);
    }
    lr_half_kernel<<<(DFFv * Dv + 255) / 256, 256>>>(left_w, right_w, G + G_L, G + G_R); // 5
    repack_last_h<<<(Dv * DFFv + 255) / 256, 256>>>(last_w, G + G_WL);                   // 6

    // 7. block-diag input projections (split precision)
    mma_proj_kernel<<<dim3(BT / 128, 1, 32), 256, GSMEM3>>>(
        G + G_XNH, G + G_XNL, G + G_XIFH, G + G_XIFL, G + G_WTH, G + G_WTL,
        F + F_WZ, F + F_WI, F + F_WF, F + F_WO, bz, bi, bf, bo);

    // 8. sLSTM scan
    int write_states = (out_size >= (int)(BTD + 4 * Bv * Dv)) ? 1 : 0;
    scan_kernel<<<128, 128>>>(Rz, Ri, Rf, Ro, F + F_WZ, F + F_WI, F + F_WF, F + F_WO,
                              F + F_HSEQ, out + BTD, write_states);

    // 9/10. hskip = LN(hseq; gn) + x ; hn = LN(hskip; ln) -> fp16 hi/lo
    ln_kernel<<<BT, 256>>>(F + F_HSEQ, gn_g, gn_b, x, F + F_HSKIP, nullptr, nullptr);
    ln_kernel<<<BT, 256>>>(F + F_HSKIP, ln_g, ln_b, nullptr, nullptr, G + G_HNH, G + G_HNL);

    // 11/12. GLU up-projections (B plain)
    {
        GArgs a;
        a.Ah[0] = G + G_HNH; a.Al[0] = G + G_HNL;
        a.Bw[0] = G + G_L; a.Bl[0] = nullptr;
        a.shift[0] = 0; a.npass = 1;
        a.lda = Dv; a.ldb = Dv; a.K = Dv;
        a.C = F + F_ZL; a.ldc = DFFP;
        a.bias = left_b; a.res = nullptr; a.ldres = 0;
        a.N = DFFv; a.act = 0;
        a.Oh = nullptr; a.Ol = nullptr; a.ldo = 0;
        mma_gemm2_kernel<<<dim3(BT / 128, (DFFv + 127) / 128), 256, GSMEM2>>>(a);
        a.Bw[0] = G + G_R;
        a.C = F + F_ZR; a.bias = right_b; a.act = 1;
        mma_gemm2_kernel<<<dim3(BT / 128, (DFFv + 127) / 128), 256, GSMEM2>>>(a);
    }
    mul_split<<<dim3((DFFv + 255) / 256, BT), 256>>>(F + F_ZL, F + F_ZR,
                                                     G + G_ZLH, G + G_ZLL);

    // 14. out = zl @ last_w^T + last_b + hskip (K padded to 1408, pads zero)
    {
        GArgs a;
        a.Ah[0] = G + G_ZLH; a.Al[0] = G + G_ZLL;
        a.Bw[0] = G + G_WL; a.Bl[0] = nullptr;
        a.shift[0] = 0; a.npass = 1;
        a.lda = DFFP; a.ldb = DFFP; a.K = DFFP;
        a.C = out; a.ldc = Dv;
        a.bias = last_b; a.res = F + F_HSKIP; a.ldres = Dv;
        a.N = Dv; a.act = 0;
        a.Oh = nullptr; a.Ol = nullptr; a.ldo = 0;
        mma_gemm2_kernel<<<dim3(BT / 128, Dv / 128), 256, GSMEM2>>>(a);
    }
}

// round 14
// speedup vs baseline: 1.1689x; 1.1689x over previous
#include <cuda_runtime.h>
#include <cuda_fp16.h>
#include <cstdint>

#define Bv   4
#define Tv   2048
#define Dv   1024
#define Hv   8
#define DHv  128
#define Kv   4
#define DFFv 1365
#define DFFP 1408
#define BT   (Bv*Tv)
#define BTD  ((size_t)BT*Dv)
#define BTF  ((size_t)BT*DFFP)

// ---------------- fp32 scratch ----------------
#define F_WZ    ((size_t)0)
#define F_WI    (BTD)
#define F_WF    ((size_t)2*BTD)
#define F_WO    ((size_t)3*BTD)
#define F_HSEQ  ((size_t)4*BTD)
#define F_HSKIP ((size_t)5*BTD)
#define F_ZL    ((size_t)6*BTD)
#define F_ZR    ((size_t)6*BTD + BTF)
#define F_TOTAL ((size_t)6*BTD + 2*BTF)
__device__ __align__(256) float g_f32[F_TOTAL];

// ---------------- fp16 scratch (hi/lo split planes) ----------------
#define G_XNH   ((size_t)0)
#define G_XNL   (BTD)
#define G_XIFH  ((size_t)2*BTD)
#define G_XIFL  ((size_t)3*BTD)
#define G_HNH   ((size_t)4*BTD)
#define G_HNL   ((size_t)5*BTD)
#define G_ZLH   ((size_t)6*BTD)
#define G_ZLL   ((size_t)6*BTD + BTF)
#define G_WPH   ((size_t)6*BTD + 2*BTF)
#define G_WPL   (G_WPH + (size_t)4*Dv*Dv)
#define G_WTH   (G_WPL + (size_t)4*Dv*Dv)
#define G_WTL   (G_WTH + (size_t)4*Hv*DHv*DHv)
#define G_L     (G_WTL + (size_t)4*Hv*DHv*DHv)
#define G_R     (G_L + (size_t)DFFv*Dv)
#define G_WL    (G_R + (size_t)DFFv*Dv)
#define G_TOTAL (G_WL + (size_t)Dv*DFFP)
__device__ __align__(256) __half g_f16[G_TOTAL];

__device__ __forceinline__ float gelu_exact(float x) {
    return 0.5f * x * (1.0f + erff(x * 0.70710678118654752f));
}
__device__ __forceinline__ void split2h(float v, __half& h, __half& l) {
    h = __float2half_rn(v);
    l = __float2half_rn(v - __half2float(h));
}

// ---------------- LayerNorm (+res), outputs fp32 and/or fp16 hi/lo ----------------
__global__ void ln_kernel(const float* __restrict__ in, const float* __restrict__ g,
                          const float* __restrict__ bb, const float* __restrict__ res,
                          float* __restrict__ out,
                          __half* __restrict__ oh, __half* __restrict__ ol)
{
    int row = blockIdx.x;
    int t = threadIdx.x;
    const float4 v = ((const float4*)(in + (size_t)row * Dv))[t];
    float s = v.x + v.y + v.z + v.w;
#pragma unroll
    for (int o = 16; o > 0; o >>= 1) s += __shfl_down_sync(0xffffffffu, s, o);
    __shared__ float red[8];
    __shared__ float bc[2];
    int wid = t >> 5;
    if ((t & 31) == 0) red[wid] = s;
    __syncthreads();
    if (t == 0) {
        float S = 0.f;
#pragma unroll
        for (int i = 0; i < 8; i++) S += red[i];
        bc[0] = S * (1.f / 1024.f);
    }
    __syncthreads();
    float mu = bc[0];
    float dx = v.x - mu, dy = v.y - mu, dz = v.z - mu, dw = v.w - mu;
    float q = dx*dx + dy*dy + dz*dz + dw*dw;
#pragma unroll
    for (int o = 16; o > 0; o >>= 1) q += __shfl_down_sync(0xffffffffu, q, o);
    if ((t & 31) == 0) red[wid] = q;
    __syncthreads();
    if (t == 0) {
        float Q = 0.f;
#pragma unroll
        for (int i = 0; i < 8; i++) Q += red[i];
        bc[1] = rsqrtf(Q * (1.f / 1024.f) + 1e-5f);
    }
    __syncthreads();
    float rs = bc[1];
    float4 gv = ((const float4*)g)[t];
    float4 bv = ((const float4*)bb)[t];
    float o4[4];
    o4[0] = dx * rs * gv.x + bv.x;
    o4[1] = dy * rs * gv.y + bv.y;
    o4[2] = dz * rs * gv.z + bv.z;
    o4[3] = dw * rs * gv.w + bv.w;
    if (res) {
        float4 rv = ((const float4*)(res + (size_t)row * Dv))[t];
        o4[0] += rv.x; o4[1] += rv.y; o4[2] += rv.z; o4[3] += rv.w;
    }
    if (out) {
        float4 w = make_float4(o4[0], o4[1], o4[2], o4[3]);
        ((float4*)(out + (size_t)row * Dv))[t] = w;
    }
    if (oh) {
        __half hh[4], ll[4];
#pragma unroll
        for (int i = 0; i < 4; i++) split2h(o4[i], hh[i], ll[i]);
        size_t o = (size_t)row * Dv + t * 4;
        *(uint64_t*)(oh + o) = *(uint64_t*)hh;
        *(uint64_t*)(ol + o) = *(uint64_t*)ll;
    }
}

// ---------------- weight prep ----------------
__global__ void repack_conv_split(const float* __restrict__ w,
                                  __half* __restrict__ oh, __half* __restrict__ ol)
{
    int idx = blockIdx.x * 256 + threadIdx.x;
    if (idx < 4 * Dv * Dv) {
        int k = idx >> 20;
        int rem = idx & ((1 << 20) - 1);
        int o = rem >> 10, i = rem & 1023;
        split2h(w[((size_t)(o * Dv + i)) * Kv + k], oh[idx], ol[idx]);
    }
}

__global__ void repack_bd_split(const float* __restrict__ Wz, const float* __restrict__ Wi,
                                const float* __restrict__ Wf, const float* __restrict__ Wo,
                                __half* __restrict__ oh, __half* __restrict__ ol)
{
    int idx = blockIdx.x * 256 + threadIdx.x;
    if (idx < 4 * Hv * DHv * DHv) {
        int gate = idx >> 17;
        int rem = idx & ((1 << 17) - 1);
        int head = rem >> 14;
        int rem2 = rem & ((1 << 14) - 1);
        int e = rem2 >> 7, d = rem2 & 127;
        const float* W = (gate == 0) ? Wz : (gate == 1) ? Wi : (gate == 2) ? Wf : Wo;
        split2h(W[(head * 128 + d) * 128 + e], oh[idx], ol[idx]);
    }
}

__global__ void lr_half_kernel(const float* __restrict__ lw, const float* __restrict__ rw,
                               __half* __restrict__ lo, __half* __restrict__ ro)
{
    int idx = blockIdx.x * 256 + threadIdx.x;
    if (idx < DFFv * Dv) {
        lo[idx] = __float2half_rn(lw[idx]);
        ro[idx] = __float2half_rn(rw[idx]);
    }
}

__global__ void repack_last_h(const float* __restrict__ w, __half* __restrict__ o16)
{
    int idx = blockIdx.x * 256 + threadIdx.x;
    if (idx < Dv * DFFv) {
        int o = idx / DFFv, i = idx - o * DFFv;
        o16[(size_t)o * DFFP + i] = __float2half_rn(w[idx]);
    }
}

__global__ void mul_split(const float* __restrict__ zl, const float* __restrict__ zr,
                          __half* __restrict__ oh, __half* __restrict__ ol)
{
    int c = blockIdx.x * 256 + threadIdx.x;
    if (c < DFFv) {
        size_t i = (size_t)blockIdx.y * DFFP + c;
        split2h(zl[i] * zr[i], oh[i], ol[i]);
    }
}

// ====== fp16 mma.sync GEMM: 3-pass (A+B split) or 2-pass (A split, B plain) ======
// k-chunk 32, PITCH 40 (80B rows; starts hit banks 0,20,8,28,16,4,24,12 -> conflict-free)
#define PITCH 40
#define PLANE (128 * PITCH * 2)          // 10240 B
#define GSMEM3 (2 * 4 * PLANE)           // 81920  -> 2 CTA/SM
#define GSMEM2 (2 * 3 * PLANE)           // 61440  -> 2 CTA/SM

__device__ __forceinline__ void ldsm_x4(uint32_t* r, uint32_t addr) {
    asm volatile("ldmatrix.sync.aligned.m8n8.x4.shared.b16 {%0,%1,%2,%3},[%4];"
                 : "=r"(r[0]), "=r"(r[1]), "=r"(r[2]), "=r"(r[3]) : "r"(addr));
}
__device__ __forceinline__ void ldsm_x2(uint32_t* r, uint32_t addr) {
    asm volatile("ldmatrix.sync.aligned.m8n8.x2.shared.b16 {%0,%1},[%2];"
                 : "=r"(r[0]), "=r"(r[1]) : "r"(addr));
}
__device__ __forceinline__ void mma_f16(float* d, const uint32_t* a, const uint32_t* b) {
    asm volatile("mma.sync.aligned.m16n8k16.row.col.f32.f16.f16.f32 "
                 "{%0,%1,%2,%3},{%4,%5,%6,%7},{%8,%9},{%0,%1,%2,%3};"
                 : "+f"(d[0]), "+f"(d[1]), "+f"(d[2]), "+f"(d[3])
                 : "r"(a[0]), "r"(a[1]), "r"(a[2]), "r"(a[3]), "r"(b[0]), "r"(b[1]));
}
__device__ __forceinline__ void cpa16(uint32_t dst, const void* src, bool pred) {
    int sz = pred ? 16 : 0;
    asm volatile("cp.async.cg.shared.global [%0], [%1], 16, %2;"
                 :: "r"(dst), "l"(src), "r"(sz) : "memory");
}

struct GArgs {
    const __half *Ah[4], *Al[4], *Bw[4], *Bl[4];
    int shift[4];
    int npass, lda, ldb, K;
    float* C; int ldc;
    const float* bias;
    const float* res; int ldres;
    int N; int act;                  // 0 none, 1 gelu, 2 swish
    __half *Oh, *Ol; int ldo;        // split fp16 output instead of C
};

template<bool SPLITB>
__device__ __forceinline__ void stage_chunk(uint32_t buf, const GArgs& a,
                                            int pass, int k0, int row0, int col0)
{
    const int tid = threadIdx.x;
    const int r = tid >> 1;            // 0..127
    const int half = tid & 1;          // 16 elems (32B) each
    const uint32_t dst0 = buf + r * (PITCH * 2) + half * 32;

    int shift = a.shift[pass];
    int grow = row0 + r;
    bool pA = (shift == 0) || ((grow & (Tv - 1)) >= shift);
    int arow = pA ? (grow - shift) : 0;
    const __half* sAh = a.Ah[pass] + (size_t)arow * a.lda + k0 + half * 16;
    const __half* sAl = a.Al[pass] + (size_t)arow * a.lda + k0 + half * 16;
    cpa16(dst0,      sAh,     pA);
    cpa16(dst0 + 16, sAh + 8, pA);
    cpa16(dst0 + PLANE,      sAl,     pA);
    cpa16(dst0 + PLANE + 16, sAl + 8, pA);

    int gn = col0 + r;
    bool pB = (gn < a.N);
    int brow = pB ? gn : 0;
    const __half* sB = a.Bw[pass] + (size_t)brow * a.ldb + k0 + half * 16;
    cpa16(dst0 + 2 * PLANE,      sB,     pB);
    cpa16(dst0 + 2 * PLANE + 16, sB + 8, pB);
    if (SPLITB) {
        const __half* sBl = a.Bl[pass] + (size_t)brow * a.ldb + k0 + half * 16;
        cpa16(dst0 + 3 * PLANE,      sBl,     pB);
        cpa16(dst0 + 3 * PLANE + 16, sBl + 8, pB);
    }
}

template<bool SPLITB>
__device__ void mma_gemm_body(const GArgs& a, int bm, int bn)
{
    constexpr int BSZ = (SPLITB ? 4 : 3) * PLANE;
    extern __shared__ char dsm[];
    const uint32_t sb = (uint32_t)__cvta_generic_to_shared(dsm);
    const int tid = threadIdx.x;
    const int lane = tid & 31;
    const int warp = tid >> 5;
    const int wm = warp & 3;
    const int wn = warp >> 2;
    const int row0 = bm * 128, col0 = bn * 128;

    const int lr = lane & 7, lg = lane >> 3;
    const int a_base = (wm * 32 + lr + (lg & 1) * 8) * PITCH + (lg >> 1) * 8;
    const int b_base = (wn * 64 + lr) * PITCH + (lg & 1) * 8;

    float acc[2][8][4];
#pragma unroll
    for (int i = 0; i < 2; i++)
#pragma unroll
        for (int j = 0; j < 8; j++)
#pragma unroll
            for (int q = 0; q < 4; q++) acc[i][j][q] = 0.f;

    const int nchunk = a.K >> 5;
    const int NIT = a.npass * nchunk;

    stage_chunk<SPLITB>(sb, a, 0, 0, row0, col0);
    asm volatile("cp.async.commit_group;" ::: "memory");

    for (int it = 0; it < NIT; it++) {
        if (it + 1 < NIT) {
            int nx = it + 1;
            int pass = nx / nchunk;
            int k0 = (nx - pass * nchunk) << 5;
            stage_chunk<SPLITB>(sb + ((nx & 1) ? BSZ : 0), a, pass, k0, row0, col0);
            asm volatile("cp.async.commit_group;" ::: "memory");
            asm volatile("cp.async.wait_group 1;" ::: "memory");
        } else {
            asm volatile("cp.async.wait_group 0;" ::: "memory");
        }
        __syncthreads();

        const uint32_t buf = sb + ((it & 1) ? BSZ : 0);
#pragma unroll
        for (int ks = 0; ks < 32; ks += 16) {
            uint32_t ah[2][4], al[2][4];
#pragma unroll
            for (int am = 0; am < 2; am++) {
                int ei = a_base + am * 16 * PITCH + ks;
                ldsm_x4(ah[am], buf + ei * 2);
                ldsm_x4(al[am], buf + PLANE + ei * 2);
            }
#pragma unroll
            for (int bi = 0; bi < 8; bi++) {
                uint32_t bh[2], bl[2];
                int ei = b_base + bi * 8 * PITCH + ks;
                ldsm_x2(bh, buf + 2 * PLANE + ei * 2);
                if (SPLITB) ldsm_x2(bl, buf + 3 * PLANE + ei * 2);
#pragma unroll
                for (int am = 0; am < 2; am++) {
                    float* d = acc[am][bi];
                    mma_f16(d, ah[am], bh);
                    if (SPLITB) mma_f16(d, ah[am], bl);
                    mma_f16(d, al[am], bh);
                }
            }
        }
        __syncthreads();
    }

    // ---- epilogue ----
#pragma unroll
    for (int am = 0; am < 2; am++) {
#pragma unroll
        for (int bi = 0; bi < 8; bi++) {
            int gr0 = row0 + wm * 32 + am * 16 + (lane >> 2);
            int gc = col0 + wn * 64 + bi * 8 + (lane & 3) * 2;
            float* d = acc[am][bi];
#pragma unroll
            for (int h = 0; h < 2; h++) {
                int gr = gr0 + h * 8;
                float v0 = d[h * 2 + 0], v1 = d[h * 2 + 1];
                bool ok0 = (gc < a.N), ok1 = (gc + 1 < a.N);
                if (a.bias) {
                    if (ok0) v0 += a.bias[gc];
                    if (ok1) v1 += a.bias[gc + 1];
                }
                if (a.act == 1) { v0 = gelu_exact(v0); v1 = gelu_exact(v1); }
                else if (a.act == 2) {
                    v0 = v0 / (1.f + expf(-v0));
                    v1 = v1 / (1.f + expf(-v1));
                }
                if (a.Oh) {
                    size_t o = (size_t)gr * a.ldo + gc;
                    __half hh, ll;
                    if (ok0) { split2h(v0, hh, ll); a.Oh[o] = hh; a.Ol[o] = ll; }
                    if (ok1) { split2h(v1, hh, ll); a.Oh[o + 1] = hh; a.Ol[o + 1] = ll; }
                } else {
                    size_t o = (size_t)gr * a.ldc + gc;
                    if (a.res) {
                        size_t ro = (size_t)gr * a.ldres + gc;
                        if (ok0) v0 += a.res[ro];
                        if (ok1) v1 += a.res[ro + 1];
                    }
                    if (ok0) a.C[o] = v0;
                    if (ok1) a.C[o + 1] = v1;
                }
            }
        }
    }
}

__global__ void __launch_bounds__(256, 2)
mma_gemm3_kernel(GArgs a)   // 3-pass, B split
{
    mma_gemm_body<true>(a, blockIdx.x, blockIdx.y);
}

__global__ void __launch_bounds__(256, 2)
mma_gemm2_kernel(GArgs a)   // 2-pass, B plain
{
    mma_gemm_body<false>(a, blockIdx.x, blockIdx.y);
}

__global__ void __launch_bounds__(256, 2)
mma_proj_kernel(const __half* xnh, const __half* xnl,
                const __half* xifh, const __half* xifl,
                const __half* wth, const __half* wtl,
                float* wz, float* wi, float* wf, float* wo,
                const float* bz, const float* bi, const float* bf, const float* bo)
{
    int z = blockIdx.z;
    int gate = z >> 3, head = z & 7;
    GArgs a;
    bool useif = (gate == 1 || gate == 2);
    a.Ah[0] = (useif ? xifh : xnh) + head * 128;
    a.Al[0] = (useif ? xifl : xnl) + head * 128;
    a.Bw[0] = wth + (size_t)z * 16384;
    a.Bl[0] = wtl + (size_t)z * 16384;
    a.shift[0] = 0; a.npass = 1;
    a.lda = Dv; a.ldb = 128; a.K = 128;
    float* Cs = (gate == 0) ? wz : (gate == 1) ? wi : (gate == 2) ? wf : wo;
    const float* bs = (gate == 0) ? bz : (gate == 1) ? bi : (gate == 2) ? bf : bo;
    a.C = Cs + head * 128; a.ldc = Dv;
    a.bias = bs + head * 128;
    a.res = nullptr; a.ldres = 0;
    a.N = 128; a.act = 0;
    a.Oh = nullptr; a.Ol = nullptr; a.ldo = 0;
    mma_gemm_body<true>(a, blockIdx.x, 0);
}

// ---------------- sLSTM scan: tagged DSMEM exchange, no cluster barrier ----------
__device__ __forceinline__ uint32_t smem_u32(const void* p) {
    return (uint32_t)__cvta_generic_to_shared(p);
}
__device__ __forceinline__ uint32_t mapa_u32(uint32_t addr, uint32_t rank) {
    uint32_t r;
    asm("mapa.shared::cluster.u32 %0, %1, %2;" : "=r"(r) : "r"(addr), "r"(rank));
    return r;
}
__device__ __forceinline__ uint32_t ctarank() {
    uint32_t r; asm("mov.u32 %0, %%cluster_ctarank;" : "=r"(r)); return r;
}
__device__ __forceinline__ void cluster_sync_() {
    asm volatile("barrier.cluster.arrive.aligned;" ::: "memory");
    asm volatile("barrier.cluster.wait.aligned;" ::: "memory");
}
__device__ __forceinline__ void st_cluster_b64(uint32_t addr, unsigned long long v) {
    asm volatile("st.shared::cluster.b64 [%0], %1;" :: "r"(addr), "l"(v) : "memory");
}
__device__ __forceinline__ float poll64(uint32_t addr, uint32_t tag) {
    uint32_t lo, hi;
    do {
        asm volatile("ld.volatile.shared.v2.u32 {%0,%1},[%2];"
                     : "=r"(lo), "=r"(hi) : "r"(addr));
    } while (hi != tag);
    return __uint_as_float(lo);
}

__global__ void __cluster_dims__(4, 1, 1) __launch_bounds__(128, 1)
scan_kernel(const float* __restrict__ Rz, const float* __restrict__ Ri,
            const float* __restrict__ Rf, const float* __restrict__ Ro,
            const float* __restrict__ wz, const float* __restrict__ wi,
            const float* __restrict__ wf, const float* __restrict__ wo,
            float* __restrict__ hseq, float* __restrict__ stout, int write_states)
{
    __shared__ float sm_h[2][128];
    __shared__ __align__(8) unsigned long long sm_slot[2][4][128];

    const int e = threadIdx.x;
    const uint32_t rank = ctarank();               // 0=z 1=i 2=f 3=o
    const int cid = blockIdx.x >> 2;
    const int b = cid >> 3, head = cid & 7;

    const float* Rsel = (rank == 0) ? Rz : (rank == 1) ? Ri : (rank == 2) ? Rf : Ro;
    const float* wsel = (rank == 0) ? wz : (rank == 1) ? wi : (rank == 2) ? wf : wo;

    float Rcol[128];
#pragma unroll
    for (int d = 0; d < 128; d++) Rcol[d] = Rsel[(head * 128 + d) * 128 + e];

    sm_h[0][e] = 0.f;
    sm_h[1][e] = 0.f;
#pragma unroll
    for (int p = 0; p < 2; p++)
#pragma unroll
        for (int g = 0; g < 4; g++) sm_slot[p][g][e] = 0xFFFFFFFFFFFFFFFFULL;

    float c = 0.f, n = 0.f, m = 0.f;

    uint32_t myaddr = smem_u32(&sm_slot[0][rank][e]);
    uint32_t dst[4];
#pragma unroll
    for (int r = 0; r < 4; r++) dst[r] = mapa_u32(myaddr, (uint32_t)r);

    uint32_t pbase[4];
#pragma unroll
    for (int g = 0; g < 4; g++) pbase[g] = smem_u32(&sm_slot[0][g][e]);

    const float* wptr = wsel + ((size_t)b * Tv) * Dv + head * 128 + e;
    float* hout = hseq + ((size_t)b * Tv) * Dv + head * 128 + e;

    __syncthreads();
    cluster_sync_();        // slots initialized cluster-wide before any store

    float wv = wptr[0];
    for (int t = 0; t < Tv; t++) {
        const int rp = t & 1;
        const float4* h4 = (const float4*)sm_h[rp];
        float a0 = 0.f, a1 = 0.f, a2 = 0.f, a3 = 0.f;
#pragma unroll
        for (int d = 0; d < 32; d++) {
            float4 hv = h4[d];
            a0 = fmaf(hv.x, Rcol[4 * d + 0], a0);
            a1 = fmaf(hv.y, Rcol[4 * d + 1], a1);
            a2 = fmaf(hv.z, Rcol[4 * d + 2], a2);
            a3 = fmaf(hv.w, Rcol[4 * d + 3], a3);
        }
        float bar = wv + ((a0 + a1) + (a2 + a3));

        const uint32_t tag = (uint32_t)(t + 1);
        unsigned long long pkt = ((unsigned long long)tag << 32) | __float_as_uint(bar);
        const uint32_t poff = (uint32_t)rp * (4 * 128 * 8);
#pragma unroll
        for (int r = 0; r < 4; r++) st_cluster_b64(dst[r] + poff, pkt);

        if (t + 1 < Tv) wv = wptr[(size_t)(t + 1) * Dv];   // prefetch next w

        float zb = poll64(pbase[0] + poff, tag);
        float ib = poll64(pbase[1] + poff, tag);
        float fb = poll64(pbase[2] + poff, tag);
        float ob = poll64(pbase[3] + poff, tag);

        float z  = tanhf(zb);
        float o  = 1.f / (1.f + expf(-ob));
        float mn = fmaxf(fb + m, ib);
        float iv = expf(ib - mn);
        float fv = expf(fb + m - mn);
        c = fv * c + iv * z;
        n = fv * n + iv;
        m = mn;
        float h = o * (c / fmaxf(fabsf(n), 1e-8f));

        if (rank == 0) hout[(size_t)t * Dv] = h;
        sm_h[rp ^ 1][e] = h;
        __syncthreads();
    }

    if (rank == 0 && write_states) {
        int off = b * Dv + head * 128 + e;
        stout[off]          = sm_h[Tv & 1][e];
        stout[4096 + off]   = c;
        stout[8192 + off]   = n;
        stout[12288 + off]  = m;
    }
    cluster_sync_();
}

// ---------------- launch ----------------
extern "C" void kernel_launch(void* const* d_in, const int* in_sizes, int n_in,
                              void* d_out, int out_size)
{
    const float* x      = (const float*)d_in[0];
    const float* Wz     = (const float*)d_in[1];
    const float* Wi     = (const float*)d_in[2];
    const float* Wf     = (const float*)d_in[3];
    const float* Wo     = (const float*)d_in[4];
    const float* bz     = (const float*)d_in[5];
    const float* bi     = (const float*)d_in[6];
    const float* bf     = (const float*)d_in[7];
    const float* bo     = (const float*)d_in[8];
    const float* Rz     = (const float*)d_in[9];
    const float* Ri     = (const float*)d_in[10];
    const float* Rf     = (const float*)d_in[11];
    const float* Ro     = (const float*)d_in[12];
    const float* conv_w = (const float*)d_in[13];
    const float* conv_b = (const float*)d_in[14];
    const float* ln_g   = (const float*)d_in[15];
    const float* ln_b   = (const float*)d_in[16];
    const float* gn_g   = (const float*)d_in[17];
    const float* gn_b   = (const float*)d_in[18];
    const float* left_w = (const float*)d_in[19];
    const float* left_b = (const float*)d_in[20];
    const float* right_w= (const float*)d_in[21];
    const float* right_b= (const float*)d_in[22];
    const float* last_w = (const float*)d_in[23];
    const float* last_b = (const float*)d_in[24];
    float* out = (float*)d_out;

    float* F = nullptr;
    __half* G = nullptr;
    cudaGetSymbolAddress((void**)&F, g_f32);
    cudaGetSymbolAddress((void**)&G, g_f16);

    cudaFuncSetAttribute(mma_gemm3_kernel, cudaFuncAttributeMaxDynamicSharedMemorySize, GSMEM3);
    cudaFuncSetAttribute(mma_gemm2_kernel, cudaFuncAttributeMaxDynamicSharedMemorySize, GSMEM2);
    cudaFuncSetAttribute(mma_proj_kernel, cudaFuncAttributeMaxDynamicSharedMemorySize, GSMEM3);

    // my launch #4 (conv GEMM) lands under ncu -s 5 -c 1
    ln_kernel<<<BT, 256>>>(x, ln_g, ln_b, nullptr, nullptr, G + G_XNH, G + G_XNL);       // 1
    repack_conv_split<<<(4 * Dv * Dv + 255) / 256, 256>>>(conv_w, G + G_WPH, G + G_WPL); // 2
    repack_bd_split<<<(4 * Hv * DHv * DHv + 255) / 256, 256>>>(Wz, Wi, Wf, Wo,
                                                               G + G_WTH, G + G_WTL);    // 3
    // 4. causal conv: 4 shift-passes fused (3-pass precision), + swish + split
    {
        GArgs a;
        for (int k = 0; k < 4; k++) {
            a.Ah[k] = G + G_XNH; a.Al[k] = G + G_XNL;
            a.Bw[k] = G + G_WPH + (size_t)k * Dv * Dv;
            a.Bl[k] = G + G_WPL + (size_t)k * Dv * Dv;
            a.shift[k] = 3 - k;
        }
        a.npass = 4; a.lda = Dv; a.ldb = Dv; a.K = Dv;
        a.C = nullptr; a.ldc = 0;
        a.bias = conv_b; a.res = nullptr; a.ldres = 0;
        a.N = Dv; a.act = 2;
        a.Oh = G + G_XIFH; a.Ol = G + G_XIFL; a.ldo = Dv;
        mma_gemm3_kernel<<<dim3(BT / 128, Dv / 128), 256, GSMEM3>>>(a);
    }
    lr_half_kernel<<<(DFFv * Dv + 255) / 256, 256>>>(left_w, right_w, G + G_L, G + G_R); // 5
    repack_last_h<<<(Dv * DFFv + 255) / 256, 256>>>(last_w, G + G_WL);                   // 6

    // 7. block-diag input projections (3-pass precision)
    mma_proj_kernel<<<dim3(BT / 128, 1, 32), 256, GSMEM3>>>(
        G + G_XNH, G + G_XNL, G + G_XIFH, G + G_XIFL, G + G_WTH, G + G_WTL,
        F + F_WZ, F + F_WI, F + F_WF, F + F_WO, bz, bi, bf, bo);

    // 8. sLSTM scan
    int write_states = (out_size >= (int)(BTD + 4 * Bv * Dv)) ? 1 : 0;
    scan_kernel<<<128, 128>>>(Rz, Ri, Rf, Ro, F + F_WZ, F + F_WI, F + F_WF, F + F_WO,
                              F + F_HSEQ, out + BTD, write_states);

    // 9/10. hskip = LN(hseq; gn) + x ; hn = LN(hskip; ln) -> fp16 hi/lo
    ln_kernel<<<BT, 256>>>(F + F_HSEQ, gn_g, gn_b, x, F + F_HSKIP, nullptr, nullptr);
    ln_kernel<<<BT, 256>>>(F + F_HSKIP, ln_g, ln_b, nullptr, nullptr, G + G_HNH, G + G_HNL);

    // 11/12. GLU up-projections (2-pass)
    {
        GArgs a;
        a.Ah[0] = G + G_HNH; a.Al[0] = G + G_HNL;
        a.Bw[0] = G + G_L; a.Bl[0] = nullptr;
        a.shift[0] = 0; a.npass = 1;
        a.lda = Dv; a.ldb = Dv; a.K = Dv;
        a.C = F + F_ZL; a.ldc = DFFP;
        a.bias = left_b; a.res = nullptr; a.ldres = 0;
        a.N = DFFv; a.act = 0;
        a.Oh = nullptr; a.Ol = nullptr; a.ldo = 0;
        mma_gemm2_kernel<<<dim3(BT / 128, (DFFv + 127) / 128), 256, GSMEM2>>>(a);
        a.Bw[0] = G + G_R;
        a.C = F + F_ZR; a.bias = right_b; a.act = 1;
        mma_gemm2_kernel<<<dim3(BT / 128, (DFFv + 127) / 128), 256, GSMEM2>>>(a);
    }
    mul_split<<<dim3((DFFv + 255) / 256, BT), 256>>>(F + F_ZL, F + F_ZR,
                                                     G + G_ZLH, G + G_ZLL);

    // 14. out = zl @ last_w^T + last_b + hskip (2-pass; K padded to 1408, pads zero)
    {
        GArgs a;
        a.Ah[0] = G + G_ZLH; a.Al[0] = G + G_ZLL;
        a.Bw[0] = G + G_WL; a.Bl[0] = nullptr;
        a.shift[0] = 0; a.npass = 1;
        a.lda = DFFP; a.ldb = DFFP; a.K = DFFP;
        a.C = out; a.ldc = Dv;
        a.bias = last_b; a.res = F + F_HSKIP; a.ldres = Dv;
        a.N = Dv; a.act = 0;
        a.Oh = nullptr; a.Ol = nullptr; a.ldo = 0;
        mma_gemm2_kernel<<<dim3(BT / 128, Dv / 128), 256, GSMEM2>>>(a);
    }
}